// round 1
// baseline (speedup 1.0000x reference)
#include <cuda_runtime.h>
#include <float.h>

// ---------------- problem constants ----------------
#define BB   2
#define V_   12000
#define VP   12001          // V + dummy vertex
#define LSP  16
#define M_TOT (BB*VP)       // 24002 rows in all vertex-major GEMMs
#define NCHUNK 94           // ceil(12000/128)

// ---------------- scratch (device globals; no allocations allowed) ----------------
__device__ float g_pfs  [BB*VP*256];   // relu(x @ W_point), dummy row zero
__device__ float g_t256a[BB*VP*256];   // res1 hidden / later h1
__device__ float g_t256b[BB*VP*256];   // res1 output
__device__ float g_f128a[BB*VP*128];   // fs (ping)
__device__ float g_f128b[BB*VP*128];   // h of res blocks / later h2
__device__ float g_part [BB*NCHUNK*128];
__device__ float g_gfs  [BB*128];
__device__ float g_gterm[BB*256];

// ---------------- flags ----------------
enum { F_RELU = 1, F_ACC = 2, F_ZDUM = 4, F_AVEC = 8 };

// ---------------- generic fused (gather-)GEMM ----------------
// out[m, n] = epilogue( sum_k A_row(m)[k] * W[k, n] )
//   gather mode (idx != null): A_row(m)[k] = X[b, idx[v*L + (k>>logC)], k & (C-1)]
//   plain  mode: A_row(m)[k] = A[(b*Va + min(v,Va-1))*lda + k]
// m -> (b = m/VP, v = m%VP)
__global__ __launch_bounds__(256)
void gemm_k(const float* __restrict__ A, const float* __restrict__ W,
            float* __restrict__ out,
            const int* __restrict__ idx,
            const float* __restrict__ bias,       // [N] or null
            const float* __restrict__ bias_b,     // [B, N] or null
            const float* __restrict__ residual,   // same layout as out, or null
            int M, int N, int K, int Va, int lda, int ldw, int ldo,
            int logC, int flags)
{
    const int BM = 128, BN = 64, BK = 16;
    __shared__ float As[BK][BM + 4];
    __shared__ float Bs[BK][BN];

    const int t   = threadIdx.x;
    const int bm0 = blockIdx.x * BM;
    const int bn0 = blockIdx.y * BN;

    // ---- A-load assignment: 2 rows per thread, one float4 (16B of K) each
    const int lrow0 = t >> 2;          // 0..63  (second row = +64)
    const int lc4   = (t & 3) * 4;     // k offset within tile: 0,4,8,12

    const float* abase[2];
    const int*   ibase[2];
#pragma unroll
    for (int r = 0; r < 2; r++) {
        int row = lrow0 + r * 64;
        int m = bm0 + row; if (m >= M) m = M - 1;
        int b = m / VP;
        int v = m - b * VP;
        if (idx) {
            abase[r] = A + b * VP * lda;        // gather source: [B, VP, C]
            ibase[r] = idx + v * LSP;
        } else {
            int va = v; if (va > Va - 1) va = Va - 1;
            abase[r] = A + (b * Va + va) * lda;
            ibase[r] = nullptr;
        }
    }

    const int tx = t & 15, ty = t >> 4;
    float acc[8][4];
#pragma unroll
    for (int i = 0; i < 8; i++)
#pragma unroll
        for (int j = 0; j < 4; j++) acc[i][j] = 0.f;

    const int cmask = (1 << logC) - 1;

    for (int k0 = 0; k0 < K; k0 += BK) {
        // ---- load A tile (transposed into smem)
#pragma unroll
        for (int r = 0; r < 2; r++) {
            int row = lrow0 + r * 64;
            const float* src;
            if (idx) {
                int l  = k0 >> logC;
                int gi = ibase[r][l];
                src = abase[r] + gi * lda + (k0 & cmask) + lc4;
            } else {
                src = abase[r] + k0 + lc4;
            }
            float4 val;
            if ((flags & F_AVEC) && (k0 + BK <= K)) {
                val = *(const float4*)src;
            } else {
                val.x = (k0 + lc4 + 0 < K) ? src[0] : 0.f;
                val.y = (k0 + lc4 + 1 < K) ? src[1] : 0.f;
                val.z = (k0 + lc4 + 2 < K) ? src[2] : 0.f;
                val.w = (k0 + lc4 + 3 < K) ? src[3] : 0.f;
            }
            As[lc4 + 0][row] = val.x;
            As[lc4 + 1][row] = val.y;
            As[lc4 + 2][row] = val.z;
            As[lc4 + 3][row] = val.w;
        }
        // ---- load B tile
        {
            int kk = t >> 4;
            int nn = (t & 15) * 4;
            float4 v;
            if (k0 + kk < K) v = *(const float4*)(W + (k0 + kk) * ldw + bn0 + nn);
            else             v = make_float4(0.f, 0.f, 0.f, 0.f);
            *(float4*)&Bs[kk][nn] = v;
        }
        __syncthreads();

#pragma unroll
        for (int kk = 0; kk < BK; kk++) {
            float4 a0 = *(const float4*)&As[kk][ty * 8];
            float4 a1 = *(const float4*)&As[kk][ty * 8 + 4];
            float4 bv = *(const float4*)&Bs[kk][tx * 4];
            float a[8] = {a0.x, a0.y, a0.z, a0.w, a1.x, a1.y, a1.z, a1.w};
            float b[4] = {bv.x, bv.y, bv.z, bv.w};
#pragma unroll
            for (int i = 0; i < 8; i++)
#pragma unroll
                for (int j = 0; j < 4; j++)
                    acc[i][j] = fmaf(a[i], b[j], acc[i][j]);
        }
        __syncthreads();
    }

    // ---- epilogue
#pragma unroll
    for (int i = 0; i < 8; i++) {
        int m = bm0 + ty * 8 + i;
        if (m >= M) continue;
        int b = m / VP;
        int v = m - b * VP;
        bool zd = (flags & F_ZDUM) && (v == VP - 1);
#pragma unroll
        for (int j = 0; j < 4; j++) {
            int n = bn0 + tx * 4 + j;
            if (n >= N) continue;
            float val = acc[i][j];
            if (bias)     val += bias[n];
            if (bias_b)   val += bias_b[b * N + n];
            if (residual) val += residual[m * ldo + n];
            if (flags & F_ACC) val += out[m * ldo + n];
            if (flags & F_RELU) val = fmaxf(val, 0.f);
            if (zd) val = 0.f;
            out[m * ldo + n] = val;
        }
    }
}

// ---------------- masked global max-pool over v < V_ ----------------
__global__ void maxpool1(const float* __restrict__ f)
{
    int chunk = blockIdx.x, b = blockIdx.y, n = threadIdx.x;  // 128 threads
    int v0 = chunk * 128;
    float m = -FLT_MAX;
    for (int i = 0; i < 128; i++) {
        int v = v0 + i;
        if (v < V_) m = fmaxf(m, f[(b * VP + v) * 128 + n]);
    }
    g_part[(b * NCHUNK + chunk) * 128 + n] = m;
}
__global__ void maxpool2()
{
    int b = blockIdx.x, n = threadIdx.x;
    float m = -FLT_MAX;
    for (int c = 0; c < NCHUNK; c++) m = fmaxf(m, g_part[(b * NCHUNK + c) * 128 + n]);
    g_gfs[b * 128 + n] = m;
}

// ---------------- gterm[b, n] = sum_c gfs[b,c] * Wo1[384+c, n] ----------------
__global__ void gterm_k(const float* __restrict__ Wo1)
{
    int b = blockIdx.x, n = threadIdx.x;   // 256 threads
    float s = 0.f;
    for (int c = 0; c < 128; c++)
        s = fmaf(g_gfs[b * 128 + c], Wo1[(384 + c) * 256 + n], s);
    g_gterm[b * 256 + n] = s;
}

// ---------------- final out = h2 @ Wo3 + bo3, v < V_ only ----------------
__global__ void out_k(const float* __restrict__ h2, const float* __restrict__ Wo3,
                      const float* __restrict__ bo3, float* __restrict__ out)
{
    __shared__ float w[384];
    int t = threadIdx.x;                    // 128 threads = 4 warps
    if (t < 128) { w[t] = Wo3[t]; w[t + 128] = Wo3[t + 128]; w[t + 256] = Wo3[t + 256]; }
    __syncthreads();
    int warp = t >> 5, lane = t & 31;
    int u = blockIdx.x * 4 + warp;          // vertex id in [0, B*V)
    if (u >= BB * V_) return;
    int b = u / V_, v = u - b * V_;
    const float* hrow = h2 + (b * VP + v) * 128;
    float s0 = 0.f, s1 = 0.f, s2 = 0.f;
    for (int c = lane; c < 128; c += 32) {
        float h = hrow[c];
        s0 = fmaf(h, w[c * 3 + 0], s0);
        s1 = fmaf(h, w[c * 3 + 1], s1);
        s2 = fmaf(h, w[c * 3 + 2], s2);
    }
    for (int o = 16; o > 0; o >>= 1) {
        s0 += __shfl_down_sync(0xffffffffu, s0, o);
        s1 += __shfl_down_sync(0xffffffffu, s1, o);
        s2 += __shfl_down_sync(0xffffffffu, s2, o);
    }
    if (lane == 0) {
        out[u * 3 + 0] = s0 + bo3[0];
        out[u * 3 + 1] = s1 + bo3[1];
        out[u * 3 + 2] = s2 + bo3[2];
    }
}

// ---------------- host-side orchestration ----------------
static inline void launch_gemm(const float* A, const float* W, float* o,
                               const int* idx, const float* bias, const float* bias_b,
                               const float* res, int N, int K, int Va, int lda,
                               int ldw, int logC, int flags)
{
    dim3 grid((M_TOT + 127) / 128, N / 64);
    gemm_k<<<grid, 256>>>(A, W, o, idx, bias, bias_b, res,
                          M_TOT, N, K, Va, lda, ldw, N, logC, flags);
}

extern "C" void kernel_launch(void* const* d_in, const int* in_sizes, int n_in,
                              void* d_out, int out_size)
{
    (void)in_sizes; (void)n_in; (void)out_size;
    const float* x       = (const float*)d_in[0];
    const int*   sidx    = (const int*)  d_in[1];
    const float* W_point = (const float*)d_in[2];
    const float* res1_W  = (const float*)d_in[3];
    const float* res1_b  = (const float*)d_in[4];
    const float* W_mid   = (const float*)d_in[5];
    const float* ress_W  = (const float*)d_in[6];
    const float* ress_b  = (const float*)d_in[7];
    const float* Wo1     = (const float*)d_in[8];
    const float* bo1     = (const float*)d_in[9];
    const float* Wo2     = (const float*)d_in[10];
    const float* bo2     = (const float*)d_in[11];
    const float* Wo3     = (const float*)d_in[12];
    const float* bo3     = (const float*)d_in[13];
    float* out = (float*)d_out;

    float *pfs, *t256a, *t256b, *f128a, *f128b, *gterm;
    cudaGetSymbolAddress((void**)&pfs,   g_pfs);
    cudaGetSymbolAddress((void**)&t256a, g_t256a);
    cudaGetSymbolAddress((void**)&t256b, g_t256b);
    cudaGetSymbolAddress((void**)&f128a, g_f128a);
    cudaGetSymbolAddress((void**)&f128b, g_f128b);
    cudaGetSymbolAddress((void**)&gterm, g_gterm);

    // 1) pfs = relu(x @ W_point), dummy row zeroed.  K=479 (odd) -> scalar A loads.
    launch_gemm(x, W_point, pfs, nullptr, nullptr, nullptr, nullptr,
                256, 479, V_, 479, 256, 0, F_RELU | F_ZDUM);

    // 2) res1 conv1: h = relu(gather(pfs) @ W0 + b0)
    launch_gemm(pfs, res1_W, t256a, sidx, res1_b, nullptr, nullptr,
                256, 16 * 256, VP, 256, 256, 8, F_RELU | F_ZDUM | F_AVEC);
    // 3) res1 conv2 + residual: r1 = relu(gather(h) @ W1 + b1 + pfs)
    launch_gemm(t256a, res1_W + 4096 * 256, t256b, sidx, res1_b + 256, nullptr, pfs,
                256, 16 * 256, VP, 256, 256, 8, F_RELU | F_ZDUM | F_AVEC);

    // 4) fs = (r1 @ W_mid) * zp
    launch_gemm(t256b, W_mid, f128a, nullptr, nullptr, nullptr, nullptr,
                128, 256, VP, 256, 128, 0, F_ZDUM | F_AVEC);

    // 5) gfs = max over v < V
    maxpool1<<<dim3(NCHUNK, BB), 128>>>(f128a);
    maxpool2<<<BB, 128>>>();

    // 6) three residual blocks at C=128 (conv2 writes fs in place; safe: A is f128b)
    for (int i = 0; i < 3; i++) {
        const float* W0 = ress_W + (i * 2 + 0) * 2048 * 128;
        const float* W1 = ress_W + (i * 2 + 1) * 2048 * 128;
        const float* b0 = ress_b + (i * 2 + 0) * 128;
        const float* b1 = ress_b + (i * 2 + 1) * 128;
        launch_gemm(f128a, W0, f128b, sidx, b0, nullptr, nullptr,
                    128, 16 * 128, VP, 128, 128, 7, F_RELU | F_ZDUM | F_AVEC);
        launch_gemm(f128b, W1, f128a, sidx, b1, nullptr, f128a,
                    128, 16 * 128, VP, 128, 128, 7, F_RELU | F_ZDUM | F_AVEC);
    }

    // 7) gterm[b] = gfs[b] @ Wo1[384:512]
    gterm_k<<<BB, 256>>>(Wo1);

    // 8) h1 pass 1: pfs @ Wo1[0:256] + bo1 + gterm
    launch_gemm(pfs, Wo1, t256a, nullptr, bo1, gterm, nullptr,
                256, 256, VP, 256, 256, 0, F_AVEC);
    // 9) h1 pass 2 (accumulate + relu): += fs @ Wo1[256:384]
    launch_gemm(f128a, Wo1 + 256 * 256, t256a, nullptr, nullptr, nullptr, nullptr,
                256, 128, VP, 128, 256, 0, F_ACC | F_RELU | F_AVEC);

    // 10) h2 = relu(h1 @ Wo2 + bo2)
    launch_gemm(t256a, Wo2, f128b, nullptr, bo2, nullptr, nullptr,
                128, 256, VP, 256, 128, 0, F_RELU | F_AVEC);

    // 11) out = h2 @ Wo3 + bo3 (non-dummy rows only)
    out_k<<<(BB * V_ + 3) / 4, 128>>>(f128b, Wo3, bo3, out);
}